// round 2
// baseline (speedup 1.0000x reference)
#include <cuda_runtime.h>

#define BB 2
#define SS 2048
#define DM 1024
#define NH 16
#define DK 64

// Scratch (device-global arrays: allowed; no allocation APIs anywhere).
static __device__ float g_Q[BB * SS * DM];
static __device__ float g_K[BB * SS * DM];
static __device__ float g_V[BB * SS * DM];
static __device__ float g_C[BB * SS * DM];

// Batched 128x64-tile GEMM, 256 threads, 8x4 micro-tile per thread.
//   BT=true : C = A * B^T  (A[M,K] row-major, B[N,K] row-major)
//   BT=false: C = A * B    (A[M,K] row-major, B[K,N] row-major)
// Batch over grid.z = b*NH + h with per-b / per-h element strides.
// Requires: M % 128 == 0, N % 64 == 0, K % 16 == 0 (true for all calls here).
template <bool BT>
__global__ __launch_bounds__(256) void gemm128x64(
    const float* __restrict__ Ag, int lda, long sAb, long sAh,
    const float* __restrict__ Bg, int ldb, long sBb, long sBh,
    float* __restrict__ Cg, int ldc, long sCb, long sCh,
    int K, float scale, const float* __restrict__ bias)
{
    const int z = blockIdx.z;
    const int b = z / NH, h = z % NH;

    const float* A = Ag + (long)b * sAb + (long)h * sAh + (long)blockIdx.y * 128 * lda;
    const float* Bp = Bg + (long)b * sBb + (long)h * sBh;
    if (BT) Bp += (long)blockIdx.x * 64 * ldb;   // rows of B
    else    Bp += blockIdx.x * 64;               // cols of B
    float* C = Cg + (long)b * sCb + (long)h * sCh
                  + (long)blockIdx.y * 128 * ldc + blockIdx.x * 64;

    __shared__ float As[16][128];
    __shared__ float Bs[16][64];

    const int tid = threadIdx.x;
    const int tx = tid & 15, ty = tid >> 4;  // tx: n (16x4=64), ty: m (16x8=128)
    float acc[8][4] = {};

    for (int k0 = 0; k0 < K; k0 += 16) {
        // A tile [128m x 16k] -> As[k][m]; each thread: 2 float4 loads along k.
        {
            int m0 = tid >> 2, kq = (tid & 3) << 2;
            #pragma unroll
            for (int r = 0; r < 2; r++) {
                int m = m0 + r * 64;
                float4 v = *(const float4*)(A + (long)m * lda + k0 + kq);
                As[kq + 0][m] = v.x; As[kq + 1][m] = v.y;
                As[kq + 2][m] = v.z; As[kq + 3][m] = v.w;
            }
        }
        if (BT) {
            // B tile [64n x 16k] -> Bs[k][n]; one float4 along k per thread.
            int n = tid >> 2, kq = (tid & 3) << 2;
            float4 v = *(const float4*)(Bp + (long)n * ldb + k0 + kq);
            Bs[kq + 0][n] = v.x; Bs[kq + 1][n] = v.y;
            Bs[kq + 2][n] = v.z; Bs[kq + 3][n] = v.w;
        } else {
            // B tile [16k x 64n] row-major -> Bs[k][n]; one float4 along n.
            int kq = tid >> 4, n = (tid & 15) << 2;
            *(float4*)&Bs[kq][n] = *(const float4*)(Bp + (long)(k0 + kq) * ldb + n);
        }
        __syncthreads();

        #pragma unroll
        for (int kk = 0; kk < 16; kk++) {
            float4 a0 = *(const float4*)&As[kk][ty << 3];
            float4 a1 = *(const float4*)&As[kk][(ty << 3) + 4];
            float4 b4 = *(const float4*)&Bs[kk][tx << 2];
            float ar[8] = {a0.x, a0.y, a0.z, a0.w, a1.x, a1.y, a1.z, a1.w};
            float br[4] = {b4.x, b4.y, b4.z, b4.w};
            #pragma unroll
            for (int i = 0; i < 8; i++)
                #pragma unroll
                for (int j = 0; j < 4; j++)
                    acc[i][j] = fmaf(ar[i], br[j], acc[i][j]);
        }
        __syncthreads();
    }

    float bv4[4] = {0.f, 0.f, 0.f, 0.f};
    if (bias) {
        #pragma unroll
        for (int j = 0; j < 4; j++) bv4[j] = bias[blockIdx.x * 64 + (tx << 2) + j];
    }
    #pragma unroll
    for (int i = 0; i < 8; i++) {
        int m = (ty << 3) + i;
        float4 o;
        o.x = fmaf(acc[i][0], scale, bv4[0]);
        o.y = fmaf(acc[i][1], scale, bv4[1]);
        o.z = fmaf(acc[i][2], scale, bv4[2]);
        o.w = fmaf(acc[i][3], scale, bv4[3]);
        *(float4*)(C + (long)m * ldc + (tx << 2)) = o;
    }
}

// Row softmax over rows of length SS=2048. One block (256 threads) per row,
// 8 elements per thread, in-place. Matches jax softmax (max-subtracted).
__global__ __launch_bounds__(256) void softmax_rows(float* __restrict__ attn)
{
    float* p = attn + (long)blockIdx.x * SS;
    const int tid = threadIdx.x;
    const int lane = tid & 31, wid = tid >> 5;
    __shared__ float red[8];

    float v[8];
    float m = -1e30f;
    #pragma unroll
    for (int i = 0; i < 8; i++) { v[i] = p[tid + i * 256]; m = fmaxf(m, v[i]); }
    #pragma unroll
    for (int o = 16; o > 0; o >>= 1) m = fmaxf(m, __shfl_xor_sync(0xffffffffu, m, o));
    if (lane == 0) red[wid] = m;
    __syncthreads();
    float mm = red[0];
    #pragma unroll
    for (int w = 1; w < 8; w++) mm = fmaxf(mm, red[w]);
    __syncthreads();

    float s = 0.f;
    #pragma unroll
    for (int i = 0; i < 8; i++) { v[i] = __expf(v[i] - mm); s += v[i]; }
    #pragma unroll
    for (int o = 16; o > 0; o >>= 1) s += __shfl_xor_sync(0xffffffffu, s, o);
    if (lane == 0) red[wid] = s;
    __syncthreads();
    float tot = red[0];
    #pragma unroll
    for (int w = 1; w < 8; w++) tot += red[w];

    float inv = 1.f / tot;
    #pragma unroll
    for (int i = 0; i < 8; i++) p[tid + i * 256] = v[i] * inv;
}

extern "C" void kernel_launch(void* const* d_in, const int* in_sizes, int n_in,
                              void* d_out, int out_size)
{
    (void)in_sizes; (void)n_in; (void)out_size;

    const float* q  = (const float*)d_in[0];
    const float* k  = (const float*)d_in[1];
    const float* vv = (const float*)d_in[2];
    const float* Wq = (const float*)d_in[3];
    const float* bq = (const float*)d_in[4];
    const float* Wk = (const float*)d_in[5];
    const float* bk = (const float*)d_in[6];
    const float* Wv = (const float*)d_in[7];
    const float* bv = (const float*)d_in[8];
    const float* Wo = (const float*)d_in[9];
    const float* bo = (const float*)d_in[10];

    float* out  = (float*)d_out;                 // [B,S,D] = 4,194,304 floats
    float* attn = out + (long)BB * SS * DM;      // [B,H,S,S] = 134,217,728 floats

    float *gQ, *gK, *gV, *gC;
    cudaGetSymbolAddress((void**)&gQ, g_Q);
    cudaGetSymbolAddress((void**)&gK, g_K);
    cudaGetSymbolAddress((void**)&gV, g_V);
    cudaGetSymbolAddress((void**)&gC, g_C);

    dim3 blk(256);
    dim3 gproj(DM / 64, (BB * SS) / 128, 1);     // (16, 32)

    // Q/K/V projections: X @ W^T + b  (NT gemm, M=4096, N=1024, K=1024)
    gemm128x64<true><<<gproj, blk>>>(q,  DM, 0, 0, Wq, DM, 0, 0, gQ, DM, 0, 0, DM, 1.f, bq);
    gemm128x64<true><<<gproj, blk>>>(k,  DM, 0, 0, Wk, DM, 0, 0, gK, DM, 0, 0, DM, 1.f, bk);
    gemm128x64<true><<<gproj, blk>>>(vv, DM, 0, 0, Wv, DM, 0, 0, gV, DM, 0, 0, DM, 1.f, bv);

    // Scores: attn[b,h,i,j] = (Qh_i . Kh_j) / 8   (NT, M=N=2048, K=64, batch=32)
    dim3 gsc(SS / 64, SS / 128, BB * NH);
    gemm128x64<true><<<gsc, blk>>>(gQ, DM, (long)SS * DM, DK,
                                   gK, DM, (long)SS * DM, DK,
                                   attn, SS, (long)NH * SS * SS, (long)SS * SS,
                                   DK, 0.125f, nullptr);

    // Softmax in place, row-wise over last dim.
    softmax_rows<<<BB * NH * SS, blk>>>(attn);

    // Context: ctx[b,i,h*64+d] = sum_j P[b,h,i,j] * V[b,j,h*64+d]
    // (NN, M=2048, N=64, K=2048, batch=32)
    dim3 gct(1, SS / 128, BB * NH);
    gemm128x64<false><<<gct, blk>>>(attn, SS, (long)NH * SS * SS, (long)SS * SS,
                                    gV, DM, (long)SS * DM, DK,
                                    gC, DM, (long)SS * DM, DK,
                                    SS, 1.f, nullptr);

    // Output projection: out = ctx @ Wo^T + bo
    gemm128x64<true><<<gproj, blk>>>(gC, DM, 0, 0, Wo, DM, 0, 0, out, DM, 0, 0, DM, 1.f, bo);
}

// round 3
// speedup vs baseline: 2.0880x; 2.0880x over previous
#include <cuda_runtime.h>

#define BB 2
#define SS 2048
#define DM 1024
#define NH 16
#define DK 64

// Scratch (device-global arrays: allowed; no allocation APIs anywhere).
static __device__ float g_Q[BB * SS * DM];
static __device__ float g_K[BB * SS * DM];
static __device__ float g_V[BB * SS * DM];
static __device__ float g_C[BB * SS * DM];

__device__ __forceinline__ unsigned f2tf(float x) {
    unsigned r;
    asm("cvt.rna.tf32.f32 %0, %1;" : "=r"(r) : "f"(x));
    return r;
}

// Batched 128x64-tile tf32 tensor-core GEMM. 256 threads = 8 warps (4 m x 2 n),
// warp tile 32x32 = 2x4 mma.m16n8k8 tiles. BK=32, 1-deep register prefetch.
//   BT=true : C = A * B^T  (A[M,K] row-major, B[N,K] row-major)
//   BT=false: C = A * B    (A[M,K] row-major, B[K,N] row-major)
// Batch over grid.z = b*NH + h with per-b / per-h element strides.
// Requires M%128==0, N%64==0, K%32==0 (true for all calls here).
#define ASTR 36   // As row stride (words): 36%32=4 -> frag bank = 4*gid+tig (bijective)
#define BSTR 72   // Bs row stride (words): 72%32=8 -> frag bank = 8*tig+gid (bijective)

template <bool BT>
__global__ __launch_bounds__(256) void gemm_tf32(
    const float* __restrict__ Ag, int lda, long sAb, long sAh,
    const float* __restrict__ Bg, int ldb, long sBb, long sBh,
    float* __restrict__ Cg, int ldc, long sCb, long sCh,
    int K, float scale, const float* __restrict__ bias)
{
    const int z = blockIdx.z;
    const int b = z / NH, h = z % NH;

    const float* A = Ag + (long)b * sAb + (long)h * sAh + (long)blockIdx.y * 128 * lda;
    const float* Bp = Bg + (long)b * sBb + (long)h * sBh;
    if (BT) Bp += (long)blockIdx.x * 64 * ldb;   // rows of B
    else    Bp += blockIdx.x * 64;               // cols of B
    float* C = Cg + (long)b * sCb + (long)h * sCh
                  + (long)blockIdx.y * 128 * ldc + blockIdx.x * 64;

    __shared__ unsigned As[128 * ASTR];
    __shared__ unsigned Bs[32 * BSTR];

    const int tid  = threadIdx.x;
    const int lane = tid & 31;
    const int w    = tid >> 5;
    const int wm   = (w & 3) << 5;   // warp row offset (0,32,64,96)
    const int wn   = (w >> 2) << 5;  // warp col offset (0,32)
    const int gid  = lane >> 2, tig = lane & 3;

    // gmem load mapping
    const int am = tid >> 3;         // 0..31 (A row within pass)
    const int ak = (tid & 7) << 2;   // 0..28 (k quad)
    const int bnr = tid >> 3;        // BT: B row (n) within pass
    const int bkr = tid >> 4;        // NN: B row (k) within pass
    const int bn4 = (tid & 15) << 2; // NN: n quad

    float acc[2][4][4];
    #pragma unroll
    for (int i = 0; i < 2; i++)
        #pragma unroll
        for (int j = 0; j < 4; j++)
            #pragma unroll
            for (int c = 0; c < 4; c++) acc[i][j][c] = 0.f;

    float4 ra[4], rb[2];

    // prefetch chunk 0
    #pragma unroll
    for (int r = 0; r < 4; r++)
        ra[r] = *(const float4*)(A + (long)(am + r * 32) * lda + ak);
    if (BT) {
        #pragma unroll
        for (int r = 0; r < 2; r++)
            rb[r] = *(const float4*)(Bp + (long)(bnr + r * 32) * ldb + ak);
    } else {
        #pragma unroll
        for (int r = 0; r < 2; r++)
            rb[r] = *(const float4*)(Bp + (long)(bkr + r * 16) * ldb + bn4);
    }

    for (int k0 = 0; k0 < K; k0 += 32) {
        // stage current chunk into smem (converted to tf32)
        #pragma unroll
        for (int r = 0; r < 4; r++) {
            unsigned* p = &As[(am + r * 32) * ASTR + ak];
            p[0] = f2tf(ra[r].x); p[1] = f2tf(ra[r].y);
            p[2] = f2tf(ra[r].z); p[3] = f2tf(ra[r].w);
        }
        if (BT) {
            #pragma unroll
            for (int r = 0; r < 2; r++) {
                int n = bnr + r * 32;
                Bs[(ak + 0) * BSTR + n] = f2tf(rb[r].x);
                Bs[(ak + 1) * BSTR + n] = f2tf(rb[r].y);
                Bs[(ak + 2) * BSTR + n] = f2tf(rb[r].z);
                Bs[(ak + 3) * BSTR + n] = f2tf(rb[r].w);
            }
        } else {
            #pragma unroll
            for (int r = 0; r < 2; r++) {
                unsigned* p = &Bs[(bkr + r * 16) * BSTR + bn4];
                p[0] = f2tf(rb[r].x); p[1] = f2tf(rb[r].y);
                p[2] = f2tf(rb[r].z); p[3] = f2tf(rb[r].w);
            }
        }
        __syncthreads();

        // prefetch next chunk
        if (k0 + 32 < K) {
            #pragma unroll
            for (int r = 0; r < 4; r++)
                ra[r] = *(const float4*)(A + (long)(am + r * 32) * lda + k0 + 32 + ak);
            if (BT) {
                #pragma unroll
                for (int r = 0; r < 2; r++)
                    rb[r] = *(const float4*)(Bp + (long)(bnr + r * 32) * ldb + k0 + 32 + ak);
            } else {
                #pragma unroll
                for (int r = 0; r < 2; r++)
                    rb[r] = *(const float4*)(Bp + (long)(k0 + 32 + bkr + r * 16) * ldb + bn4);
            }
        }

        // compute: 4 k8 steps
        #pragma unroll
        for (int k8 = 0; k8 < 4; k8++) {
            unsigned af[2][4], bf[4][2];
            #pragma unroll
            for (int mi = 0; mi < 2; mi++) {
                int r0 = wm + mi * 16 + gid;
                int c0 = k8 * 8 + tig;
                af[mi][0] = As[r0 * ASTR + c0];
                af[mi][1] = As[(r0 + 8) * ASTR + c0];
                af[mi][2] = As[r0 * ASTR + c0 + 4];
                af[mi][3] = As[(r0 + 8) * ASTR + c0 + 4];
            }
            #pragma unroll
            for (int ni = 0; ni < 4; ni++) {
                int cc = wn + ni * 8 + gid;
                int rr = k8 * 8 + tig;
                bf[ni][0] = Bs[rr * BSTR + cc];
                bf[ni][1] = Bs[(rr + 4) * BSTR + cc];
            }
            #pragma unroll
            for (int mi = 0; mi < 2; mi++)
                #pragma unroll
                for (int ni = 0; ni < 4; ni++) {
                    asm volatile(
                        "mma.sync.aligned.m16n8k8.row.col.f32.tf32.tf32.f32 "
                        "{%0,%1,%2,%3}, {%4,%5,%6,%7}, {%8,%9}, {%0,%1,%2,%3};"
                        : "+f"(acc[mi][ni][0]), "+f"(acc[mi][ni][1]),
                          "+f"(acc[mi][ni][2]), "+f"(acc[mi][ni][3])
                        : "r"(af[mi][0]), "r"(af[mi][1]), "r"(af[mi][2]), "r"(af[mi][3]),
                          "r"(bf[ni][0]), "r"(bf[ni][1]));
                }
        }
        __syncthreads();
    }

    // epilogue: c0:(g,2t) c1:(g,2t+1) c2:(g+8,2t) c3:(g+8,2t+1)
    #pragma unroll
    for (int mi = 0; mi < 2; mi++) {
        int r0 = wm + mi * 16 + gid;
        #pragma unroll
        for (int ni = 0; ni < 4; ni++) {
            int c0 = wn + ni * 8 + (tig << 1);
            float bv0 = 0.f, bv1 = 0.f;
            if (bias) {
                bv0 = bias[blockIdx.x * 64 + c0];
                bv1 = bias[blockIdx.x * 64 + c0 + 1];
            }
            float2 v0, v1;
            v0.x = fmaf(acc[mi][ni][0], scale, bv0);
            v0.y = fmaf(acc[mi][ni][1], scale, bv1);
            v1.x = fmaf(acc[mi][ni][2], scale, bv0);
            v1.y = fmaf(acc[mi][ni][3], scale, bv1);
            *(float2*)(C + (long)r0 * ldc + c0) = v0;
            *(float2*)(C + (long)(r0 + 8) * ldc + c0) = v1;
        }
    }
}

// Row softmax over rows of length SS=2048. One block (256 threads) per row,
// 8 elements per thread, in-place.
__global__ __launch_bounds__(256) void softmax_rows(float* __restrict__ attn)
{
    float* p = attn + (long)blockIdx.x * SS;
    const int tid = threadIdx.x;
    const int lane = tid & 31, wid = tid >> 5;
    __shared__ float red[8];

    float v[8];
    float m = -1e30f;
    #pragma unroll
    for (int i = 0; i < 8; i++) { v[i] = p[tid + i * 256]; m = fmaxf(m, v[i]); }
    #pragma unroll
    for (int o = 16; o > 0; o >>= 1) m = fmaxf(m, __shfl_xor_sync(0xffffffffu, m, o));
    if (lane == 0) red[wid] = m;
    __syncthreads();
    float mm = red[0];
    #pragma unroll
    for (int w = 1; w < 8; w++) mm = fmaxf(mm, red[w]);
    __syncthreads();

    float s = 0.f;
    #pragma unroll
    for (int i = 0; i < 8; i++) { v[i] = __expf(v[i] - mm); s += v[i]; }
    #pragma unroll
    for (int o = 16; o > 0; o >>= 1) s += __shfl_xor_sync(0xffffffffu, s, o);
    if (lane == 0) red[wid] = s;
    __syncthreads();
    float tot = red[0];
    #pragma unroll
    for (int w = 1; w < 8; w++) tot += red[w];

    float inv = 1.f / tot;
    #pragma unroll
    for (int i = 0; i < 8; i++) p[tid + i * 256] = v[i] * inv;
}

extern "C" void kernel_launch(void* const* d_in, const int* in_sizes, int n_in,
                              void* d_out, int out_size)
{
    (void)in_sizes; (void)n_in; (void)out_size;

    const float* q  = (const float*)d_in[0];
    const float* k  = (const float*)d_in[1];
    const float* vv = (const float*)d_in[2];
    const float* Wq = (const float*)d_in[3];
    const float* bq = (const float*)d_in[4];
    const float* Wk = (const float*)d_in[5];
    const float* bk = (const float*)d_in[6];
    const float* Wv = (const float*)d_in[7];
    const float* bv = (const float*)d_in[8];
    const float* Wo = (const float*)d_in[9];
    const float* bo = (const float*)d_in[10];

    float* out  = (float*)d_out;                 // [B,S,D] = 4,194,304 floats
    float* attn = out + (long)BB * SS * DM;      // [B,H,S,S] = 134,217,728 floats

    float *gQ, *gK, *gV, *gC;
    cudaGetSymbolAddress((void**)&gQ, g_Q);
    cudaGetSymbolAddress((void**)&gK, g_K);
    cudaGetSymbolAddress((void**)&gV, g_V);
    cudaGetSymbolAddress((void**)&gC, g_C);

    dim3 blk(256);
    dim3 gproj(DM / 64, (BB * SS) / 128, 1);     // (16, 32)

    // Q/K/V projections: X @ W^T + b  (NT, M=4096, N=1024, K=1024)
    gemm_tf32<true><<<gproj, blk>>>(q,  DM, 0, 0, Wq, DM, 0, 0, gQ, DM, 0, 0, DM, 1.f, bq);
    gemm_tf32<true><<<gproj, blk>>>(k,  DM, 0, 0, Wk, DM, 0, 0, gK, DM, 0, 0, DM, 1.f, bk);
    gemm_tf32<true><<<gproj, blk>>>(vv, DM, 0, 0, Wv, DM, 0, 0, gV, DM, 0, 0, DM, 1.f, bv);

    // Scores: attn[b,h,i,j] = (Qh_i . Kh_j) / 8   (NT, M=N=2048, K=64, batch=32)
    dim3 gsc(SS / 64, SS / 128, BB * NH);
    gemm_tf32<true><<<gsc, blk>>>(gQ, DM, (long)SS * DM, DK,
                                  gK, DM, (long)SS * DM, DK,
                                  attn, SS, (long)NH * SS * SS, (long)SS * SS,
                                  DK, 0.125f, nullptr);

    // Softmax in place, row-wise over last dim.
    softmax_rows<<<BB * NH * SS, blk>>>(attn);

    // Context: ctx[b,i,h*64+d] = sum_j P[b,h,i,j] * V[b,j,h*64+d]
    // (NN, M=2048, N=64, K=2048, batch=32)
    dim3 gct(1, SS / 128, BB * NH);
    gemm_tf32<false><<<gct, blk>>>(attn, SS, (long)NH * SS * SS, (long)SS * SS,
                                   gV, DM, (long)SS * DM, DK,
                                   gC, DM, (long)SS * DM, DK,
                                   SS, 1.f, nullptr);

    // Output projection: out = ctx @ Wo^T + bo
    gemm_tf32<true><<<gproj, blk>>>(gC, DM, 0, 0, Wo, DM, 0, 0, out, DM, 0, 0, DM, 1.f, bo);
}